// round 14
// baseline (speedup 1.0000x reference)
#include <cuda_runtime.h>
#include <cuda_bf16.h>
#include <math_constants.h>

// Problem constants
#define B       16
#define C       64
#define HW      4096
#define K       1024
#define NPIX    65536
#define QSIZE   4194304
#define OFF_LOSS 4194304
#define OFF_PERP 4194305
#define OFF_IDX  4194306
#define OFF_ENC  4259842          // *4B is 8B-aligned -> float2 stores ok
#define PPB 128                   // 4 warps
#define MPX 64                    // pixels per block
#define NBLOCKS (NPIX / MPX)      // 1024
#define CPT 128                   // codes per tile
#define NTILES (K / CPT)          // 8

// Dynamic smem layout (bytes)
#define XBF_OFF   0               // bf16 [64][72]  = 9216
#define WBF_OFF   9216            // bf16 [128][72] = 18432
#define WSQ_OFF   27648           // f32  [1024]    = 4096
#define GMIN_OFF  31744           // f32  [128][64] = 32768  (group-min per pixel)
#define X_OFF     64512           // f32  [64]
#define MARG_OFF  64768           // f32  [64]
#define THR_OFF   65024           // f32  [64]
#define FINI_OFF  65280           // int  [64]
#define REDL_OFF  65536           // f32  [4]
#define SMEM_DYN  65600

// Scratch (device globals; no allocation allowed)
__device__ int   d_counts[K];             // zero at load; re-zeroed by vq_fin
__device__ float d_loss_partial[NBLOCKS];
__device__ float d_wsq[K];
__device__ __nv_bfloat16 d_wbf[K * C];

// m16n8k16 row.col bf16 MMA, fp32 accumulate (in-place)
__device__ __forceinline__ void mma_bf16(float& c0, float& c1, float& c2, float& c3,
                                         unsigned a0, unsigned a1, unsigned a2, unsigned a3,
                                         unsigned b0, unsigned b1) {
    asm volatile(
        "mma.sync.aligned.m16n8k16.row.col.f32.bf16.bf16.f32 "
        "{%0,%1,%2,%3},{%4,%5,%6,%7},{%8,%9},{%0,%1,%2,%3};"
        : "+f"(c0), "+f"(c1), "+f"(c2), "+f"(c3)
        : "r"(a0), "r"(a1), "r"(a2), "r"(a3), "r"(b0), "r"(b1));
}

// ---------------------------------------------------------------------------
// Prep: warp-per-code ||w||^2 + bf16 copy (measured ~4.5us).
// ---------------------------------------------------------------------------
__global__ void vq_prep(const float* __restrict__ weight) {
    int w = threadIdx.x >> 5, l = threadIdx.x & 31;
    int k = blockIdx.x * 4 + w;
    float2 v = ((const float2*)(weight + (size_t)k * C))[l];
    ((__nv_bfloat162*)d_wbf)[(size_t)k * 32 + l] = __floats2bfloat162_rn(v.x, v.y);
    float s = __fadd_rn(__fmul_rn(v.x, v.x), __fmul_rn(v.y, v.y));
#pragma unroll
    for (int o = 16; o > 0; o >>= 1) s += __shfl_xor_sync(0xFFFFFFFFu, s, o);
    if (l == 0) d_wsq[k] = s;
}

// ---------------------------------------------------------------------------
// Main: single MMA sweep. Per 8-code group, the q-lane shfl min (d~ group
// min) is stored to SMEM gmin[group][pixel]. Rescore: any group with
// gmin <= tau gets all 8 codes exact-rescored (superset of true candidate
// set; NO lists, NO overflow path). Exact rescore byte-identical to the
// R2..R13 passing pipeline.
// ---------------------------------------------------------------------------
__global__ __launch_bounds__(PPB) void vq_main(const float* __restrict__ in,
                                               const float* __restrict__ weight,
                                               float* __restrict__ out) {
    extern __shared__ char smem[];
    __nv_bfloat16 (*xbf)[72]  = (__nv_bfloat16(*)[72])(smem + XBF_OFF);
    __nv_bfloat16 (*wbf)[72]  = (__nv_bfloat16(*)[72])(smem + WBF_OFF);
    float* wsq_s  = (float*)(smem + WSQ_OFF);
    float* gmin   = (float*)(smem + GMIN_OFF);    // [g][px] : g*64+px
    float* X_s    = (float*)(smem + X_OFF);
    float* marg_s = (float*)(smem + MARG_OFF);
    float* thr    = (float*)(smem + THR_OFF);
    int*   finI   = (int*)(smem + FINI_OFF);
    float* redL   = (float*)(smem + REDL_OFF);

    const int t    = threadIdx.x;
    const int lane = t & 31;
    const int wid  = t >> 5;
    const int q    = lane & 3;
    const int r    = lane >> 2;
    const int b    = blockIdx.x >> 6;
    const int p0   = (blockIdx.x & 63) * MPX;
    const float* xin = in + (size_t)b * C * HW + p0;

    // ---- x -> bf16 tile ----
#pragma unroll
    for (int i = 0; i < 32; i++) {
        int e = i * PPB + t;
        int px = e & 63, c = e >> 6;
        xbf[px][c] = __float2bfloat16(xin[(size_t)c * HW + px]);
    }
#pragma unroll
    for (int i = 0; i < 8; i++) wsq_s[i * PPB + t] = d_wsq[i * PPB + t];
    __syncthreads();

    // ---- per-pixel exact X (sequential, tie-deciding) + margin ----
    if (t < MPX) {
        float X = 0.f, S = 0.f;
#pragma unroll
        for (int c = 0; c < C; c++) {
            float v = xin[(size_t)c * HW + t];
            X = __fadd_rn(X, __fmul_rn(v, v));
            S += fabsf(v);
        }
        X_s[t] = X;
        marg_s[t] = 4.f * (S * 7.62939453e-6f) + 1e-4f;   // 4E + 1e-4
    }

    // ---- A fragments: warp wid owns pixels [16*wid, +16) ----
    const int rbase = wid * 16 + r;
    unsigned a[4][4];
#pragma unroll
    for (int k0i = 0; k0i < 4; k0i++) {
        int k0 = k0i * 16;
        a[k0i][0] = *(const unsigned*)&xbf[rbase][k0 + 2 * q];
        a[k0i][1] = *(const unsigned*)&xbf[rbase + 8][k0 + 2 * q];
        a[k0i][2] = *(const unsigned*)&xbf[rbase][k0 + 2 * q + 8];
        a[k0i][3] = *(const unsigned*)&xbf[rbase + 8][k0 + 2 * q + 8];
    }

    float2* encz = (float2*)(out + OFF_ENC + (size_t)blockIdx.x * MPX * K);
    const float2 z2 = make_float2(0.f, 0.f);
    float min0 = CUDART_INF_F, min1 = CUDART_INF_F;   // pixel runmin (all q lanes)

    // =================== SINGLE MMA SWEEP ===================
#pragma unroll 1
    for (int tile = 0; tile < NTILES; tile++) {
        __syncthreads();
#pragma unroll
        for (int i = 0; i < 32; i++) {           // wbf tile: uint-copies
            int e = i * PPB + t;
            int cp = e & 31, code = e >> 5;
            *(unsigned*)&wbf[code][2 * cp] =
                ((const unsigned*)d_wbf)[((size_t)tile * CPT + code) * 32 + cp];
        }
        __syncthreads();
        // enc zeroing rides here (32KB per tile)
#pragma unroll
        for (int i = 0; i < 32; i++) encz[tile * 4096 + i * PPB + t] = z2;

#pragma unroll 1
        for (int nc = 0; nc < 16; nc++) {
            const int kb = tile * CPT + nc * 8;
            const int cr = nc * 8 + r;
            float c0 = 0.f, c1 = 0.f, c2 = 0.f, c3 = 0.f;
#pragma unroll
            for (int k0i = 0; k0i < 4; k0i++) {
                unsigned b0 = *(const unsigned*)&wbf[cr][k0i * 16 + 2 * q];
                unsigned b1 = *(const unsigned*)&wbf[cr][k0i * 16 + 2 * q + 8];
                mma_bf16(c0, c1, c2, c3, a[k0i][0], a[k0i][1], a[k0i][2], a[k0i][3], b0, b1);
            }
            float w0 = wsq_s[kb + 2 * q], w1 = wsq_s[kb + 2 * q + 1];
            float g0 = fminf(fmaf(-2.f, c0, w0), fmaf(-2.f, c1, w1));
            float g1 = fminf(fmaf(-2.f, c2, w0), fmaf(-2.f, c3, w1));
            // group min across the 4 q lanes (8 codes)
            g0 = fminf(g0, __shfl_xor_sync(0xFFFFFFFFu, g0, 1));
            g0 = fminf(g0, __shfl_xor_sync(0xFFFFFFFFu, g0, 2));
            g1 = fminf(g1, __shfl_xor_sync(0xFFFFFFFFu, g1, 1));
            g1 = fminf(g1, __shfl_xor_sync(0xFFFFFFFFu, g1, 2));
            min0 = fminf(min0, g0);
            min1 = fminf(min1, g1);
            if (q == 0) {
                const int g = tile * 16 + nc;
                gmin[g * MPX + rbase]     = g0;
                gmin[g * MPX + rbase + 8] = g1;
            }
        }
    }
    // all q lanes hold the pixel min (group mins were shfl-broadcast)
    if (q == 0) {
        thr[rbase]     = min0 + marg_s[rbase];
        thr[rbase + 8] = min1 + marg_s[rbase + 8];
    }
    __syncthreads();   // gmin + thr visible; enc zero-chunks complete

    // ====== rescore: exact-rescore all 8 codes of every flagged group ======
    if (t < MPX) {
        const float X = X_s[t];
        const float tau = thr[t];
        float best = CUDART_INF_F; int bk = 0;
#pragma unroll 1
        for (int g = 0; g < K / 8; g++) {
            if (gmin[g * MPX + t] <= tau) {
#pragma unroll 1
                for (int kk = 0; kk < 8; kk++) {
                    const int k = g * 8 + kk;
                    const float* wk = weight + (size_t)k * C;
                    float m = 0.f;
#pragma unroll
                    for (int c = 0; c < C; c++) m = fmaf(xin[(size_t)c * HW + t], wk[c], m);
                    float d = __fsub_rn(__fadd_rn(X, wsq_s[k]), __fadd_rn(m, m));
                    if (d < best || (d == best && k < bk)) { best = d; bk = k; }
                }
            }
        }
        finI[t] = bk;
    }
    __syncthreads();

    // =================== epilogue ===================
    {
        const int px = t & 63;
        const int hf = t >> 6;                   // channel half
        const int bk = finI[px];
        const float* wb = weight + (size_t)bk * C + hf * 32;
        const float* xi = xin + (size_t)hf * 32 * HW + px;
        float* outq = out + (size_t)b * C * HW + (size_t)hf * 32 * HW + p0 + px;
        float lsum = 0.f;
#pragma unroll
        for (int c = 0; c < 32; c++) {
            float xv = xi[(size_t)c * HW];
            float dd = __fsub_rn(wb[c], xv);
            outq[(size_t)c * HW] = __fadd_rn(xv, dd);   // STE
            lsum = fmaf(dd, dd, lsum);
        }
        if (t < MPX) {
            const int n = blockIdx.x * MPX + t;
            out[OFF_IDX + n] = (float)finI[t];
            out[OFF_ENC + (size_t)n * K + finI[t]] = 1.0f;
            atomicAdd(&d_counts[finI[t]], 1);
        }
#pragma unroll
        for (int o = 16; o > 0; o >>= 1) lsum += __shfl_down_sync(0xFFFFFFFFu, lsum, o);
        if ((t & 31) == 0) redL[t >> 5] = lsum;
        __syncthreads();
        if (t == 0) d_loss_partial[blockIdx.x] = (redL[0] + redL[1]) + (redL[2] + redL[3]);
    }
}

// ---------------------------------------------------------------------------
// Finalize: loss + perplexity; re-zeroes d_counts for the next graph replay.
// ---------------------------------------------------------------------------
__global__ void vq_fin(float* __restrict__ out) {
    __shared__ float sh[K];
    __shared__ float sh2[NBLOCKS];
    int t = threadIdx.x;                  // 1024

    int cnt = d_counts[t];
    d_counts[t] = 0;
    float pr = (float)cnt * (1.0f / (float)NPIX);
    sh[t] = pr * logf(pr + 1e-10f);
    sh2[t] = d_loss_partial[t];
    __syncthreads();

    for (int s = K / 2; s > 0; s >>= 1) {
        if (t < s) { sh[t] += sh[t + s]; sh2[t] += sh2[t + s]; }
        __syncthreads();
    }
    if (t == 0) {
        out[OFF_LOSS] = 0.25f * sh2[0] / (float)QSIZE;
        out[OFF_PERP] = expf(-sh[0]);
    }
}

// ---------------------------------------------------------------------------
extern "C" void kernel_launch(void* const* d_in, const int* in_sizes, int n_in,
                              void* d_out, int out_size) {
    const float* in     = (const float*)d_in[0];
    const float* weight = (const float*)d_in[1];
    float* out = (float*)d_out;

    // opt-in >48KB dynamic smem (idempotent; immediate host-side call)
    cudaFuncSetAttribute(vq_main, cudaFuncAttributeMaxDynamicSharedMemorySize, SMEM_DYN);

    vq_prep<<<256, 128>>>(weight);
    vq_main<<<NBLOCKS, PPB, SMEM_DYN>>>(in, weight, out);
    vq_fin<<<1, K>>>(out);
}

// round 15
// speedup vs baseline: 4.0223x; 4.0223x over previous
#include <cuda_runtime.h>
#include <cuda_bf16.h>
#include <cuda_fp16.h>
#include <math_constants.h>

// Problem constants
#define B       16
#define C       64
#define HW      4096
#define K       1024
#define NPIX    65536
#define QSIZE   4194304
#define OFF_LOSS 4194304
#define OFF_PERP 4194305
#define OFF_IDX  4194306
#define OFF_ENC  4259842          // *4B is 8B-aligned -> float2 stores ok
#define PPB 128                   // 4 warps
#define MPX 64                    // pixels per block
#define NBLOCKS (NPIX / MPX)      // 1024
#define CPT 128                   // codes per tile
#define NTILES (K / CPT)          // 8
#define MAXCAND 16                // pairs (= up to 32 codes)

// Scratch (device globals; no allocation allowed)
__device__ int   d_counts[K];             // zero at load; re-zeroed by vq_fin
__device__ float d_loss_partial[NBLOCKS];
__device__ float d_wsq[K];
__device__ __nv_bfloat16 d_wbf[K * C];
// lane-pair-min f16 scratch: (block,tile,nc,wid,lane) -> half2 (px0min, px1min)
__device__ unsigned d_scr[NBLOCKS * NTILES * 16 * 4 * 32];   // 64MB

// m16n8k16 row.col bf16 MMA, fp32 accumulate (in-place)
__device__ __forceinline__ void mma_bf16(float& c0, float& c1, float& c2, float& c3,
                                         unsigned a0, unsigned a1, unsigned a2, unsigned a3,
                                         unsigned b0, unsigned b1) {
    asm volatile(
        "mma.sync.aligned.m16n8k16.row.col.f32.bf16.bf16.f32 "
        "{%0,%1,%2,%3},{%4,%5,%6,%7},{%8,%9},{%0,%1,%2,%3};"
        : "+f"(c0), "+f"(c1), "+f"(c2), "+f"(c3)
        : "r"(a0), "r"(a1), "r"(a2), "r"(a3), "r"(b0), "r"(b1));
}

// ---------------------------------------------------------------------------
// Prep: warp-per-code ||w||^2 + bf16 copy (measured ~4us).
// ---------------------------------------------------------------------------
__global__ void vq_prep(const float* __restrict__ weight) {
    int w = threadIdx.x >> 5, l = threadIdx.x & 31;
    int k = blockIdx.x * 4 + w;
    float2 v = ((const float2*)(weight + (size_t)k * C))[l];
    ((__nv_bfloat162*)d_wbf)[(size_t)k * 32 + l] = __floats2bfloat162_rn(v.x, v.y);
    float s = __fadd_rn(__fmul_rn(v.x, v.x), __fmul_rn(v.y, v.y));
#pragma unroll
    for (int o = 16; o > 0; o >>= 1) s += __shfl_xor_sync(0xFFFFFFFFu, s, o);
    if (l == 0) d_wsq[k] = s;
}

// ---------------------------------------------------------------------------
// Main (R13 structure, halved scratch): pass 1 = MMA sweep, store
// f16(min of the lane's 2 codes) per pixel, track pixel min on the SAME
// rounded values; pass 2 = coalesced scratch replay, flag pairs <= tau,
// exact-rescore BOTH codes of each flagged pair (superset -> sound).
// NO shfl in the MMA inner loop (R9/R14 lesson). Exact rescore identical
// to the R2..R13 passing pipeline.
// ---------------------------------------------------------------------------
__global__ __launch_bounds__(PPB) void vq_main(const float* __restrict__ in,
                                               const float* __restrict__ weight,
                                               float* __restrict__ out) {
    __shared__ __nv_bfloat16 xbf[MPX][72];
    __shared__ __nv_bfloat16 wbf[CPT][72];
    __shared__ float wsq_s[K];
    __shared__ float X_s[MPX], S_s[MPX], minD[MPX], thr[MPX];
    __shared__ int   candCnt[MPX];
    __shared__ short candL[MPX][MAXCAND];
    __shared__ int   finI[MPX];
    __shared__ float redL[4];
    __shared__ float ovD[4];  __shared__ int ovK[4];
    __shared__ int   ovList[MPX]; __shared__ int ovCnt;

    const int t    = threadIdx.x;
    const int lane = t & 31;
    const int wid  = t >> 5;
    const int q    = lane & 3;
    const int r    = lane >> 2;
    const int b    = blockIdx.x >> 6;
    const int p0   = (blockIdx.x & 63) * MPX;
    const float* xin = in + (size_t)b * C * HW + p0;

    // ---- x -> bf16 tile ----
#pragma unroll
    for (int i = 0; i < 32; i++) {
        int e = i * PPB + t;
        int px = e & 63, c = e >> 6;
        xbf[px][c] = __float2bfloat16(xin[(size_t)c * HW + px]);
    }
#pragma unroll
    for (int i = 0; i < 8; i++) wsq_s[i * PPB + t] = d_wsq[i * PPB + t];
    if (t < MPX) candCnt[t] = 0;
    if (t == 0) ovCnt = 0;
    __syncthreads();

    // ---- per-pixel exact X (sequential, tie-deciding) and S = sum|x| ----
    if (t < MPX) {
        float X = 0.f, S = 0.f;
#pragma unroll
        for (int c = 0; c < C; c++) {
            float v = xin[(size_t)c * HW + t];
            X = __fadd_rn(X, __fmul_rn(v, v));
            S += fabsf(v);
        }
        X_s[t] = X; S_s[t] = S;
    }

    // ---- A fragments: warp wid owns pixels [16*wid, +16) ----
    const int rbase = wid * 16 + r;
    unsigned a[4][4];
#pragma unroll
    for (int k0i = 0; k0i < 4; k0i++) {
        int k0 = k0i * 16;
        a[k0i][0] = *(const unsigned*)&xbf[rbase][k0 + 2 * q];
        a[k0i][1] = *(const unsigned*)&xbf[rbase + 8][k0 + 2 * q];
        a[k0i][2] = *(const unsigned*)&xbf[rbase][k0 + 2 * q + 8];
        a[k0i][3] = *(const unsigned*)&xbf[rbase + 8][k0 + 2 * q + 8];
    }

    float2* encz = (float2*)(out + OFF_ENC + (size_t)blockIdx.x * MPX * K);
    const float2 z2 = make_float2(0.f, 0.f);
    float min0 = CUDART_INF_F, min1 = CUDART_INF_F;

    // =================== PASS 1: MMA sweep + pair-min scratch + min ===================
#pragma unroll 1
    for (int tile = 0; tile < NTILES; tile++) {
        __syncthreads();
#pragma unroll
        for (int i = 0; i < 32; i++) {           // wbf tile: uint-copies
            int e = i * PPB + t;
            int cp = e & 31, code = e >> 5;
            *(unsigned*)&wbf[code][2 * cp] =
                ((const unsigned*)d_wbf)[((size_t)tile * CPT + code) * 32 + cp];
        }
        __syncthreads();
        // enc zeroing rides here (32KB per tile)
#pragma unroll
        for (int i = 0; i < 32; i++) encz[tile * 4096 + i * PPB + t] = z2;

        unsigned* scrT = d_scr + (((size_t)blockIdx.x * NTILES + tile) * 16) * 128;
#pragma unroll 1
        for (int nc = 0; nc < 16; nc++) {
            const int kb = tile * CPT + nc * 8;
            const int cr = nc * 8 + r;
            float c0 = 0.f, c1 = 0.f, c2 = 0.f, c3 = 0.f;
#pragma unroll
            for (int k0i = 0; k0i < 4; k0i++) {
                unsigned b0 = *(const unsigned*)&wbf[cr][k0i * 16 + 2 * q];
                unsigned b1 = *(const unsigned*)&wbf[cr][k0i * 16 + 2 * q + 8];
                mma_bf16(c0, c1, c2, c3, a[k0i][0], a[k0i][1], a[k0i][2], a[k0i][3], b0, b1);
            }
            float w0 = wsq_s[kb + 2 * q], w1 = wsq_s[kb + 2 * q + 1];
            // lane-pair min per pixel, rounded to f16 (pass 2 reads same bits)
            __half2 hm = __floats2half2_rn(
                fminf(fmaf(-2.f, c0, w0), fmaf(-2.f, c1, w1)),
                fminf(fmaf(-2.f, c2, w0), fmaf(-2.f, c3, w1)));
            scrT[nc * 128 + wid * 32 + lane] = *(unsigned*)&hm;
            float2 fm = __half22float2(hm);
            min0 = fminf(min0, fm.x);
            min1 = fminf(min1, fm.y);
        }
    }
    // pixel min across the 4 q lanes (outside the hot loop: 4 shfls TOTAL)
    min0 = fminf(min0, __shfl_xor_sync(0xFFFFFFFFu, min0, 1));
    min0 = fminf(min0, __shfl_xor_sync(0xFFFFFFFFu, min0, 2));
    min1 = fminf(min1, __shfl_xor_sync(0xFFFFFFFFu, min1, 1));
    min1 = fminf(min1, __shfl_xor_sync(0xFFFFFFFFu, min1, 2));
    if (q == 0) { minD[rbase] = min0; minD[rbase + 8] = min1; }
    __syncthreads();
    // margin: 4*E + 1e-4 (slack also covers f16 rounding ~3e-5)
    if (t < MPX) thr[t] = minD[t] + 4.f * (S_s[t] * 7.62939453e-6f) + 1e-4f;
    __syncthreads();

    // =================== PASS 2: scratch replay + collect pairs ===================
    {
        const float t0 = thr[rbase], t1 = thr[rbase + 8];
#pragma unroll 1
        for (int tile = 0; tile < NTILES; tile++) {
            unsigned* scrT = d_scr + (((size_t)blockIdx.x * NTILES + tile) * 16) * 128;
#pragma unroll
            for (int nc = 0; nc < 16; nc++) {
                unsigned v = scrT[nc * 128 + wid * 32 + lane];
                float2 f = __half22float2(*(__half2*)&v);
                const int kp = tile * CPT + nc * 8 + 2 * q;   // pair base code
                if (f.x <= t0) { int p = atomicAdd(&candCnt[rbase], 1);     if (p < MAXCAND) candL[rbase][p]     = (short)kp; }
                if (f.y <= t1) { int p = atomicAdd(&candCnt[rbase + 8], 1); if (p < MAXCAND) candL[rbase + 8][p] = (short)kp; }
            }
        }
    }
    __syncthreads();

    // ---- overflow list (R8 measured ~1.3 pairs/px; 16 is generous) ----
    if (t < MPX && candCnt[t] > MAXCAND) { int p = atomicAdd(&ovCnt, 1); ovList[p] = t; }
    __syncthreads();

    // =================== exact rescore (reference rounding) ===================
    if (t < MPX && candCnt[t] <= MAXCAND) {
        const float X = X_s[t];
        float best = CUDART_INF_F; int bk = 0;
        const int cnt = candCnt[t];
        for (int i = 0; i < cnt; i++) {
            const int kp = candL[t][i];
#pragma unroll
            for (int kk = 0; kk < 2; kk++) {      // both codes of the pair
                const int k = kp + kk;
                const float* wk = weight + (size_t)k * C;
                float m = 0.f;
#pragma unroll
                for (int c = 0; c < C; c++) m = fmaf(xin[(size_t)c * HW + t], wk[c], m);
                float d = __fsub_rn(__fadd_rn(X, wsq_s[k]), __fadd_rn(m, m));
                if (d < best || (d == best && k < bk)) { best = d; bk = k; }
            }
        }
        finI[t] = bk;
    }
    __syncthreads();

    // ---- block-cooperative exact fallback (~3us each, essentially never) ----
    for (int i = 0; i < ovCnt; i++) {
        const int px = ovList[i];
        const float X = X_s[px];
        float bd = CUDART_INF_F; int bk = 0;
#pragma unroll 1
        for (int kk = 0; kk < 8; kk++) {
            int k = t * 8 + kk;
            const float* wk = weight + (size_t)k * C;
            float m = 0.f;
#pragma unroll
            for (int c = 0; c < C; c++) m = fmaf(xin[(size_t)c * HW + px], wk[c], m);
            float d = __fsub_rn(__fadd_rn(X, wsq_s[k]), __fadd_rn(m, m));
            if (d < bd || (d == bd && k < bk)) { bd = d; bk = k; }
        }
#pragma unroll
        for (int o = 16; o > 0; o >>= 1) {
            float od = __shfl_down_sync(0xFFFFFFFFu, bd, o);
            int   ok = __shfl_down_sync(0xFFFFFFFFu, bk, o);
            if (od < bd || (od == bd && ok < bk)) { bd = od; bk = ok; }
        }
        if (lane == 0) { ovD[wid] = bd; ovK[wid] = bk; }
        __syncthreads();
        if (t == 0) {
            float fd = ovD[0]; int fk = ovK[0];
#pragma unroll
            for (int g = 1; g < 4; g++)
                if (ovD[g] < fd || (ovD[g] == fd && ovK[g] < fk)) { fd = ovD[g]; fk = ovK[g]; }
            finI[px] = fk;
        }
        __syncthreads();
    }

    // =================== epilogue ===================
    {
        const int px = t & 63;
        const int hf = t >> 6;                   // channel half
        const int bk = finI[px];
        const float* wb = weight + (size_t)bk * C + hf * 32;
        const float* xi = xin + (size_t)hf * 32 * HW + px;
        float* outq = out + (size_t)b * C * HW + (size_t)hf * 32 * HW + p0 + px;
        float lsum = 0.f;
#pragma unroll
        for (int c = 0; c < 32; c++) {
            float xv = xi[(size_t)c * HW];
            float dd = __fsub_rn(wb[c], xv);
            outq[(size_t)c * HW] = __fadd_rn(xv, dd);   // STE
            lsum = fmaf(dd, dd, lsum);
        }
        if (t < MPX) {
            const int n = blockIdx.x * MPX + t;
            out[OFF_IDX + n] = (float)finI[t];
            out[OFF_ENC + (size_t)n * K + finI[t]] = 1.0f;
            atomicAdd(&d_counts[finI[t]], 1);
        }
#pragma unroll
        for (int o = 16; o > 0; o >>= 1) lsum += __shfl_down_sync(0xFFFFFFFFu, lsum, o);
        if ((t & 31) == 0) redL[t >> 5] = lsum;
        __syncthreads();
        if (t == 0) d_loss_partial[blockIdx.x] = (redL[0] + redL[1]) + (redL[2] + redL[3]);
    }
}

// ---------------------------------------------------------------------------
// Finalize: loss + perplexity; re-zeroes d_counts for the next graph replay.
// ---------------------------------------------------------------------------
__global__ void vq_fin(float* __restrict__ out) {
    __shared__ float sh[K];
    __shared__ float sh2[NBLOCKS];
    int t = threadIdx.x;                  // 1024

    int cnt = d_counts[t];
    d_counts[t] = 0;
    float pr = (float)cnt * (1.0f / (float)NPIX);
    sh[t] = pr * logf(pr + 1e-10f);
    sh2[t] = d_loss_partial[t];
    __syncthreads();

    for (int s = K / 2; s > 0; s >>= 1) {
        if (t < s) { sh[t] += sh[t + s]; sh2[t] += sh2[t + s]; }
        __syncthreads();
    }
    if (t == 0) {
        out[OFF_LOSS] = 0.25f * sh2[0] / (float)QSIZE;
        out[OFF_PERP] = expf(-sh[0]);
    }
}

// ---------------------------------------------------------------------------
extern "C" void kernel_launch(void* const* d_in, const int* in_sizes, int n_in,
                              void* d_out, int out_size) {
    const float* in     = (const float*)d_in[0];
    const float* weight = (const float*)d_in[1];
    float* out = (float*)d_out;

    vq_prep<<<256, 128>>>(weight);
    vq_main<<<NBLOCKS, PPB>>>(in, weight, out);
    vq_fin<<<1, K>>>(out);
}

// round 16
// speedup vs baseline: 4.3297x; 1.0764x over previous
#include <cuda_runtime.h>
#include <cuda_bf16.h>
#include <cuda_fp16.h>
#include <math_constants.h>

// Problem constants
#define B       16
#define C       64
#define HW      4096
#define K       1024
#define NPIX    65536
#define QSIZE   4194304
#define OFF_LOSS 4194304
#define OFF_PERP 4194305
#define OFF_IDX  4194306
#define OFF_ENC  4259842          // *4B is 8B-aligned -> float2 stores ok
#define PPB 256                   // 8 warps
#define MPX 128                   // pixels per block
#define NBLOCKS (NPIX / MPX)      // 512
#define CPT 128                   // codes per tile
#define NTILES (K / CPT)          // 8
#define MAXCAND 16                // codes

// Scratch (device globals; no allocation allowed)
__device__ int   d_counts[K];             // zero at load; re-zeroed by vq_fin
__device__ float d_loss_partial[NBLOCKS];
__device__ float d_wsq[K];
__device__ __nv_bfloat16 d_wbf[K * C];
// fragment-ordered f16 distance scratch: (block,tile,nc,wid,h,lane) -> half2
__device__ unsigned d_scr[NBLOCKS * NTILES * 16 * 512];   // 128MB

// m16n8k16 row.col bf16 MMA, fp32 accumulate (in-place)
__device__ __forceinline__ void mma_bf16(float& c0, float& c1, float& c2, float& c3,
                                         unsigned a0, unsigned a1, unsigned a2, unsigned a3,
                                         unsigned b0, unsigned b1) {
    asm volatile(
        "mma.sync.aligned.m16n8k16.row.col.f32.bf16.bf16.f32 "
        "{%0,%1,%2,%3},{%4,%5,%6,%7},{%8,%9},{%0,%1,%2,%3};"
        : "+f"(c0), "+f"(c1), "+f"(c2), "+f"(c3)
        : "r"(a0), "r"(a1), "r"(a2), "r"(a3), "r"(b0), "r"(b1));
}

// ---------------------------------------------------------------------------
// Prep: warp-per-code ||w||^2 + bf16 copy (measured ~4us).
// ---------------------------------------------------------------------------
__global__ void vq_prep(const float* __restrict__ weight) {
    int w = threadIdx.x >> 5, l = threadIdx.x & 31;
    int k = blockIdx.x * 4 + w;
    float2 v = ((const float2*)(weight + (size_t)k * C))[l];
    ((__nv_bfloat162*)d_wbf)[(size_t)k * 32 + l] = __floats2bfloat162_rn(v.x, v.y);
    float s = __fadd_rn(__fmul_rn(v.x, v.x), __fmul_rn(v.y, v.y));
#pragma unroll
    for (int o = 16; o > 0; o >>= 1) s += __shfl_xor_sync(0xFFFFFFFFu, s, o);
    if (l == 0) d_wsq[k] = s;
}

// ---------------------------------------------------------------------------
// Main = R13 algorithm with 2x bigger blocks (8 warps, 128 pixels).
// Warp wid owns pixels [16*wid, +16). Pass 1: MMA sweep, f16 d~ to
// fragment-ordered scratch, track min on the SAME rounded values. Pass 2:
// coalesced scratch replay + final-threshold collect. Exact rescore
// byte-identical to the R2..R13 passing pipeline. No shfl in MMA loop.
// ---------------------------------------------------------------------------
__global__ __launch_bounds__(PPB) void vq_main(const float* __restrict__ in,
                                               const float* __restrict__ weight,
                                               float* __restrict__ out) {
    __shared__ __nv_bfloat16 xbf[MPX][72];       // 18.4KB
    __shared__ __nv_bfloat16 wbf[CPT][72];       // 18.4KB
    __shared__ float wsq_s[K];                   // 4KB
    __shared__ float X_s[MPX], S_s[MPX], minD[MPX], thr[MPX];
    __shared__ int   candCnt[MPX];
    __shared__ short candL[MPX][MAXCAND];        // 4KB
    __shared__ int   finI[MPX];
    __shared__ float redL[8];
    __shared__ float ovD[8];  __shared__ int ovK[8];
    __shared__ int   ovList[MPX]; __shared__ int ovCnt;

    const int t    = threadIdx.x;
    const int lane = t & 31;
    const int wid  = t >> 5;                     // 0..7
    const int q    = lane & 3;
    const int r    = lane >> 2;
    const int b    = blockIdx.x >> 5;            // 32 chunks of 128 px per plane
    const int p0   = (blockIdx.x & 31) * MPX;
    const float* xin = in + (size_t)b * C * HW + p0;

    // ---- x -> bf16 tile (128 px x 64 ch = 8192 elems) ----
#pragma unroll
    for (int i = 0; i < 32; i++) {
        int e = i * PPB + t;
        int px = e & 127, c = e >> 7;
        xbf[px][c] = __float2bfloat16(xin[(size_t)c * HW + px]);
    }
#pragma unroll
    for (int i = 0; i < 4; i++) wsq_s[i * PPB + t] = d_wsq[i * PPB + t];
    if (t < MPX) candCnt[t] = 0;
    if (t == 0) ovCnt = 0;
    __syncthreads();

    // ---- per-pixel exact X (sequential, tie-deciding) and S = sum|x| ----
    if (t < MPX) {
        float X = 0.f, S = 0.f;
#pragma unroll
        for (int c = 0; c < C; c++) {
            float v = xin[(size_t)c * HW + t];
            X = __fadd_rn(X, __fmul_rn(v, v));
            S += fabsf(v);
        }
        X_s[t] = X; S_s[t] = S;
    }

    // ---- A fragments: warp wid owns pixels [16*wid, +16) ----
    const int rbase = wid * 16 + r;
    unsigned a[4][4];
#pragma unroll
    for (int k0i = 0; k0i < 4; k0i++) {
        int k0 = k0i * 16;
        a[k0i][0] = *(const unsigned*)&xbf[rbase][k0 + 2 * q];
        a[k0i][1] = *(const unsigned*)&xbf[rbase + 8][k0 + 2 * q];
        a[k0i][2] = *(const unsigned*)&xbf[rbase][k0 + 2 * q + 8];
        a[k0i][3] = *(const unsigned*)&xbf[rbase + 8][k0 + 2 * q + 8];
    }

    float2* encz = (float2*)(out + OFF_ENC + (size_t)blockIdx.x * MPX * K);
    const float2 z2 = make_float2(0.f, 0.f);
    float min0 = CUDART_INF_F, min1 = CUDART_INF_F;

    // =================== PASS 1: MMA sweep + scratch store + min ===================
#pragma unroll 1
    for (int tile = 0; tile < NTILES; tile++) {
        __syncthreads();
#pragma unroll
        for (int i = 0; i < 16; i++) {           // wbf tile: 4096 uints
            int e = i * PPB + t;
            int cp = e & 31, code = e >> 5;
            *(unsigned*)&wbf[code][2 * cp] =
                ((const unsigned*)d_wbf)[((size_t)tile * CPT + code) * 32 + cp];
        }
        __syncthreads();
        // enc zeroing rides here (64KB per tile: block owns 512KB / 8 tiles)
#pragma unroll
        for (int i = 0; i < 32; i++) encz[tile * 8192 + i * PPB + t] = z2;

        unsigned* scrT = d_scr + (((size_t)blockIdx.x * NTILES + tile) * 16) * 512;
#pragma unroll 1
        for (int nc = 0; nc < 16; nc++) {
            const int kb = tile * CPT + nc * 8;
            const int cr = nc * 8 + r;
            float c0 = 0.f, c1 = 0.f, c2 = 0.f, c3 = 0.f;
#pragma unroll
            for (int k0i = 0; k0i < 4; k0i++) {
                unsigned b0 = *(const unsigned*)&wbf[cr][k0i * 16 + 2 * q];
                unsigned b1 = *(const unsigned*)&wbf[cr][k0i * 16 + 2 * q + 8];
                mma_bf16(c0, c1, c2, c3, a[k0i][0], a[k0i][1], a[k0i][2], a[k0i][3], b0, b1);
            }
            float w0 = wsq_s[kb + 2 * q], w1 = wsq_s[kb + 2 * q + 1];
            // round to f16 FIRST; min and pass-2 compare use the same values
            __half2 h0 = __floats2half2_rn(fmaf(-2.f, c0, w0), fmaf(-2.f, c1, w1));
            __half2 h1 = __floats2half2_rn(fmaf(-2.f, c2, w0), fmaf(-2.f, c3, w1));
            unsigned* scrNC = scrT + nc * 512 + wid * 64 + lane;
            scrNC[0]  = *(unsigned*)&h0;
            scrNC[32] = *(unsigned*)&h1;
            float2 f0 = __half22float2(h0);
            float2 f1 = __half22float2(h1);
            min0 = fminf(min0, fminf(f0.x, f0.y));
            min1 = fminf(min1, fminf(f1.x, f1.y));
        }
    }
    // pixel min across the 4 q lanes (outside the hot loop)
    min0 = fminf(min0, __shfl_xor_sync(0xFFFFFFFFu, min0, 1));
    min0 = fminf(min0, __shfl_xor_sync(0xFFFFFFFFu, min0, 2));
    min1 = fminf(min1, __shfl_xor_sync(0xFFFFFFFFu, min1, 1));
    min1 = fminf(min1, __shfl_xor_sync(0xFFFFFFFFu, min1, 2));
    if (q == 0) { minD[rbase] = min0; minD[rbase + 8] = min1; }
    __syncthreads();
    // margin: 4*E + 1e-4 (slack also covers f16 rounding ~3e-5)
    if (t < MPX) thr[t] = minD[t] + 4.f * (S_s[t] * 7.62939453e-6f) + 1e-4f;
    __syncthreads();

    // =================== PASS 2: scratch replay + collect ===================
    {
        const float t0 = thr[rbase], t1 = thr[rbase + 8];
#pragma unroll 1
        for (int tile = 0; tile < NTILES; tile++) {
            unsigned* scrT = d_scr + (((size_t)blockIdx.x * NTILES + tile) * 16) * 512;
#pragma unroll
            for (int nc = 0; nc < 16; nc++) {
                unsigned* scrNC = scrT + nc * 512 + wid * 64 + lane;
                unsigned v0 = scrNC[0];
                unsigned v1 = scrNC[32];
                float2 f0 = __half22float2(*(__half2*)&v0);
                float2 f1 = __half22float2(*(__half2*)&v1);
                const int kb = tile * CPT + nc * 8;
                if (f0.x <= t0) { int p = atomicAdd(&candCnt[rbase], 1);     if (p < MAXCAND) candL[rbase][p]     = (short)(kb + 2 * q); }
                if (f0.y <= t0) { int p = atomicAdd(&candCnt[rbase], 1);     if (p < MAXCAND) candL[rbase][p]     = (short)(kb + 2 * q + 1); }
                if (f1.x <= t1) { int p = atomicAdd(&candCnt[rbase + 8], 1); if (p < MAXCAND) candL[rbase + 8][p] = (short)(kb + 2 * q); }
                if (f1.y <= t1) { int p = atomicAdd(&candCnt[rbase + 8], 1); if (p < MAXCAND) candL[rbase + 8][p] = (short)(kb + 2 * q + 1); }
            }
        }
    }
    __syncthreads();

    // ---- overflow list (R8 measured ~1.3 cands/px; rare) ----
    if (t < MPX && candCnt[t] > MAXCAND) { int p = atomicAdd(&ovCnt, 1); ovList[p] = t; }
    __syncthreads();

    // =================== exact rescore (reference rounding) ===================
    if (t < MPX && candCnt[t] <= MAXCAND) {
        const float X = X_s[t];
        float best = CUDART_INF_F; int bk = 0;
        const int cnt = candCnt[t];
        for (int i = 0; i < cnt; i++) {
            int k = candL[t][i];
            const float* wk = weight + (size_t)k * C;
            float m = 0.f;
#pragma unroll
            for (int c = 0; c < C; c++) m = fmaf(xin[(size_t)c * HW + t], wk[c], m);
            float d = __fsub_rn(__fadd_rn(X, wsq_s[k]), __fadd_rn(m, m));
            if (d < best || (d == best && k < bk)) { best = d; bk = k; }
        }
        finI[t] = bk;
    }
    __syncthreads();

    // ---- block-cooperative exact fallback (rare) ----
    for (int i = 0; i < ovCnt; i++) {
        const int px = ovList[i];
        const float X = X_s[px];
        float bd = CUDART_INF_F; int bk = 0;
#pragma unroll 1
        for (int kk = 0; kk < 4; kk++) {
            int k = t * 4 + kk;
            const float* wk = weight + (size_t)k * C;
            float m = 0.f;
#pragma unroll
            for (int c = 0; c < C; c++) m = fmaf(xin[(size_t)c * HW + px], wk[c], m);
            float d = __fsub_rn(__fadd_rn(X, wsq_s[k]), __fadd_rn(m, m));
            if (d < bd || (d == bd && k < bk)) { bd = d; bk = k; }
        }
#pragma unroll
        for (int o = 16; o > 0; o >>= 1) {
            float od = __shfl_down_sync(0xFFFFFFFFu, bd, o);
            int   ok = __shfl_down_sync(0xFFFFFFFFu, bk, o);
            if (od < bd || (od == bd && ok < bk)) { bd = od; bk = ok; }
        }
        if (lane == 0) { ovD[wid] = bd; ovK[wid] = bk; }
        __syncthreads();
        if (t == 0) {
            float fd = ovD[0]; int fk = ovK[0];
#pragma unroll
            for (int g = 1; g < 8; g++)
                if (ovD[g] < fd || (ovD[g] == fd && ovK[g] < fk)) { fd = ovD[g]; fk = ovK[g]; }
            finI[px] = fk;
        }
        __syncthreads();
    }

    // =================== epilogue ===================
    {
        const int px = t & 127;
        const int hf = t >> 7;                   // channel half
        const int bk = finI[px];
        const float* wb = weight + (size_t)bk * C + hf * 32;
        const float* xi = xin + (size_t)hf * 32 * HW + px;
        float* outq = out + (size_t)b * C * HW + (size_t)hf * 32 * HW + p0 + px;
        float lsum = 0.f;
#pragma unroll
        for (int c = 0; c < 32; c++) {
            float xv = xi[(size_t)c * HW];
            float dd = __fsub_rn(wb[c], xv);
            outq[(size_t)c * HW] = __fadd_rn(xv, dd);   // STE
            lsum = fmaf(dd, dd, lsum);
        }
        if (t < MPX) {
            const int n = blockIdx.x * MPX + t;
            out[OFF_IDX + n] = (float)finI[t];
            out[OFF_ENC + (size_t)n * K + finI[t]] = 1.0f;
            atomicAdd(&d_counts[finI[t]], 1);
        }
#pragma unroll
        for (int o = 16; o > 0; o >>= 1) lsum += __shfl_down_sync(0xFFFFFFFFu, lsum, o);
        if (lane == 0) redL[wid] = lsum;
        __syncthreads();
        if (t == 0) {
            float s = 0.f;
#pragma unroll
            for (int g = 0; g < 8; g++) s += redL[g];
            d_loss_partial[blockIdx.x] = s;
        }
    }
}

// ---------------------------------------------------------------------------
// Finalize: loss + perplexity; re-zeroes d_counts for the next graph replay.
// ---------------------------------------------------------------------------
__global__ void vq_fin(float* __restrict__ out) {
    __shared__ float sh[K];
    __shared__ float sh2[K];
    int t = threadIdx.x;                  // 1024

    int cnt = d_counts[t];
    d_counts[t] = 0;
    float pr = (float)cnt * (1.0f / (float)NPIX);
    sh[t] = pr * logf(pr + 1e-10f);
    sh2[t] = (t < NBLOCKS) ? d_loss_partial[t] : 0.f;
    __syncthreads();

    for (int s = K / 2; s > 0; s >>= 1) {
        if (t < s) { sh[t] += sh[t + s]; sh2[t] += sh2[t + s]; }
        __syncthreads();
    }
    if (t == 0) {
        out[OFF_LOSS] = 0.25f * sh2[0] / (float)QSIZE;
        out[OFF_PERP] = expf(-sh[0]);
    }
}

// ---------------------------------------------------------------------------
extern "C" void kernel_launch(void* const* d_in, const int* in_sizes, int n_in,
                              void* d_out, int out_size) {
    const float* in     = (const float*)d_in[0];
    const float* weight = (const float*)d_in[1];
    float* out = (float*)d_out;

    vq_prep<<<256, 128>>>(weight);
    vq_main<<<NBLOCKS, PPB>>>(in, weight, out);
    vq_fin<<<1, K>>>(out);
}

// round 17
// speedup vs baseline: 4.5287x; 1.0460x over previous
#include <cuda_runtime.h>
#include <cuda_bf16.h>
#include <cuda_fp16.h>
#include <math_constants.h>

// Problem constants
#define B       16
#define C       64
#define HW      4096
#define K       1024
#define NPIX    65536
#define QSIZE   4194304
#define OFF_LOSS 4194304
#define OFF_PERP 4194305
#define OFF_IDX  4194306
#define OFF_ENC  4259842          // *4B is 8B-aligned -> float2 stores ok
#define PPB 128                   // 4 warps
#define MPX 64                    // pixels per block
#define NBLOCKS (NPIX / MPX)      // 1024
#define CPT 128                   // codes per tile
#define NTILES (K / CPT)          // 8
#define MAXCAND 16

// Scratch (device globals; no allocation allowed)
__device__ int   d_counts[K];             // zero at load; re-zeroed by vq_fin
__device__ float d_loss_partial[NBLOCKS];
__device__ float d_wsq[K];
__device__ __nv_bfloat16 d_wbf[K * C];
// fragment-ordered f16 distance scratch: (block,tile,nc,wid,h,lane) -> half2
__device__ unsigned d_scr[NBLOCKS * NTILES * 16 * 4 * 2 * 32];   // 128MB

// m16n8k16 row.col bf16 MMA, fp32 accumulate (in-place)
__device__ __forceinline__ void mma_bf16(float& c0, float& c1, float& c2, float& c3,
                                         unsigned a0, unsigned a1, unsigned a2, unsigned a3,
                                         unsigned b0, unsigned b1) {
    asm volatile(
        "mma.sync.aligned.m16n8k16.row.col.f32.bf16.bf16.f32 "
        "{%0,%1,%2,%3},{%4,%5,%6,%7},{%8,%9},{%0,%1,%2,%3};"
        : "+f"(c0), "+f"(c1), "+f"(c2), "+f"(c3)
        : "r"(a0), "r"(a1), "r"(a2), "r"(a3), "r"(b0), "r"(b1));
}

// ---------------------------------------------------------------------------
// Prep: warp-per-code ||w||^2 + bf16 copy (measured ~4us).
// ---------------------------------------------------------------------------
__global__ void vq_prep(const float* __restrict__ weight) {
    int w = threadIdx.x >> 5, l = threadIdx.x & 31;
    int k = blockIdx.x * 4 + w;
    float2 v = ((const float2*)(weight + (size_t)k * C))[l];
    ((__nv_bfloat162*)d_wbf)[(size_t)k * 32 + l] = __floats2bfloat162_rn(v.x, v.y);
    float s = __fadd_rn(__fmul_rn(v.x, v.x), __fmul_rn(v.y, v.y));
#pragma unroll
    for (int o = 16; o > 0; o >>= 1) s += __shfl_xor_sync(0xFFFFFFFFu, s, o);
    if (l == 0) d_wsq[k] = s;
}

// ---------------------------------------------------------------------------
// Main = R13 champion + micro-levers: nc-loop unroll 2 (ILP across the
// 4-deep dependent HMMA chains), streaming cache hints on scratch
// (__stcs/__ldcs) and enc-zero (__stwt). All arithmetic byte-identical
// to the R13-passing kernel.
// ---------------------------------------------------------------------------
__global__ __launch_bounds__(PPB) void vq_main(const float* __restrict__ in,
                                               const float* __restrict__ weight,
                                               float* __restrict__ out) {
    __shared__ __nv_bfloat16 xbf[MPX][72];
    __shared__ __nv_bfloat16 wbf[CPT][72];
    __shared__ float wsq_s[K];
    __shared__ float X_s[MPX], S_s[MPX], minD[MPX], thr[MPX];
    __shared__ int   candCnt[MPX];
    __shared__ short candL[MPX][MAXCAND];
    __shared__ int   finI[MPX];
    __shared__ float redL[4];
    __shared__ float ovD[4];  __shared__ int ovK[4];
    __shared__ int   ovList[MPX]; __shared__ int ovCnt;

    const int t    = threadIdx.x;
    const int lane = t & 31;
    const int wid  = t >> 5;
    const int q    = lane & 3;
    const int r    = lane >> 2;
    const int b    = blockIdx.x >> 6;
    const int p0   = (blockIdx.x & 63) * MPX;
    const float* xin = in + (size_t)b * C * HW + p0;

    // ---- x -> bf16 tile ----
#pragma unroll
    for (int i = 0; i < 32; i++) {
        int e = i * PPB + t;
        int px = e & 63, c = e >> 6;
        xbf[px][c] = __float2bfloat16(xin[(size_t)c * HW + px]);
    }
#pragma unroll
    for (int i = 0; i < 8; i++) wsq_s[i * PPB + t] = d_wsq[i * PPB + t];
    if (t < MPX) candCnt[t] = 0;
    if (t == 0) ovCnt = 0;
    __syncthreads();

    // ---- per-pixel exact X (sequential, tie-deciding) and S = sum|x| ----
    if (t < MPX) {
        float X = 0.f, S = 0.f;
#pragma unroll
        for (int c = 0; c < C; c++) {
            float v = xin[(size_t)c * HW + t];
            X = __fadd_rn(X, __fmul_rn(v, v));
            S += fabsf(v);
        }
        X_s[t] = X; S_s[t] = S;
    }

    // ---- A fragments: warp wid owns pixels [16*wid, +16) ----
    const int rbase = wid * 16 + r;
    unsigned a[4][4];
#pragma unroll
    for (int k0i = 0; k0i < 4; k0i++) {
        int k0 = k0i * 16;
        a[k0i][0] = *(const unsigned*)&xbf[rbase][k0 + 2 * q];
        a[k0i][1] = *(const unsigned*)&xbf[rbase + 8][k0 + 2 * q];
        a[k0i][2] = *(const unsigned*)&xbf[rbase][k0 + 2 * q + 8];
        a[k0i][3] = *(const unsigned*)&xbf[rbase + 8][k0 + 2 * q + 8];
    }

    float2* encz = (float2*)(out + OFF_ENC + (size_t)blockIdx.x * MPX * K);
    const float2 z2 = make_float2(0.f, 0.f);
    float min0 = CUDART_INF_F, min1 = CUDART_INF_F;

    // =================== PASS 1: MMA sweep + scratch store + min ===================
#pragma unroll 1
    for (int tile = 0; tile < NTILES; tile++) {
        __syncthreads();
#pragma unroll
        for (int i = 0; i < 32; i++) {           // wbf tile: uint-copies
            int e = i * PPB + t;
            int cp = e & 31, code = e >> 5;
            *(unsigned*)&wbf[code][2 * cp] =
                ((const unsigned*)d_wbf)[((size_t)tile * CPT + code) * 32 + cp];
        }
        __syncthreads();
        // enc zeroing rides here (32KB per tile), write-through (write-only data)
#pragma unroll
        for (int i = 0; i < 32; i++) __stwt(&encz[tile * 4096 + i * PPB + t], z2);

        unsigned* scrT = d_scr + (((size_t)blockIdx.x * NTILES + tile) * 16) * 256;
#pragma unroll 2
        for (int nc = 0; nc < 16; nc++) {
            const int kb = tile * CPT + nc * 8;
            const int cr = nc * 8 + r;
            float c0 = 0.f, c1 = 0.f, c2 = 0.f, c3 = 0.f;
#pragma unroll
            for (int k0i = 0; k0i < 4; k0i++) {
                unsigned b0 = *(const unsigned*)&wbf[cr][k0i * 16 + 2 * q];
                unsigned b1 = *(const unsigned*)&wbf[cr][k0i * 16 + 2 * q + 8];
                mma_bf16(c0, c1, c2, c3, a[k0i][0], a[k0i][1], a[k0i][2], a[k0i][3], b0, b1);
            }
            float w0 = wsq_s[kb + 2 * q], w1 = wsq_s[kb + 2 * q + 1];
            // round to f16 FIRST; min and pass-2 compare use the same values
            __half2 h0 = __floats2half2_rn(fmaf(-2.f, c0, w0), fmaf(-2.f, c1, w1));
            __half2 h1 = __floats2half2_rn(fmaf(-2.f, c2, w0), fmaf(-2.f, c3, w1));
            unsigned* scrNC = scrT + nc * 256 + wid * 64 + lane;
            __stcs(scrNC,      *(unsigned*)&h0);   // streaming: read-once later
            __stcs(scrNC + 32, *(unsigned*)&h1);
            float2 f0 = __half22float2(h0);
            float2 f1 = __half22float2(h1);
            min0 = fminf(min0, fminf(f0.x, f0.y));
            min1 = fminf(min1, fminf(f1.x, f1.y));
        }
    }
    min0 = fminf(min0, __shfl_xor_sync(0xFFFFFFFFu, min0, 1));
    min0 = fminf(min0, __shfl_xor_sync(0xFFFFFFFFu, min0, 2));
    min1 = fminf(min1, __shfl_xor_sync(0xFFFFFFFFu, min1, 1));
    min1 = fminf(min1, __shfl_xor_sync(0xFFFFFFFFu, min1, 2));
    if (q == 0) { minD[rbase] = min0; minD[rbase + 8] = min1; }
    __syncthreads();
    // margin: 4*E + 1e-4 (slack also covers f16 rounding ~3e-5)
    if (t < MPX) thr[t] = minD[t] + 4.f * (S_s[t] * 7.62939453e-6f) + 1e-4f;
    __syncthreads();

    // =================== PASS 2: scratch replay + collect ===================
    {
        const float t0 = thr[rbase], t1 = thr[rbase + 8];
#pragma unroll 1
        for (int tile = 0; tile < NTILES; tile++) {
            unsigned* scrT = d_scr + (((size_t)blockIdx.x * NTILES + tile) * 16) * 256;
#pragma unroll
            for (int nc = 0; nc < 16; nc++) {
                unsigned* scrNC = scrT + nc * 256 + wid * 64 + lane;
                unsigned v0 = __ldcs(scrNC);
                unsigned v1 = __ldcs(scrNC + 32);
                float2 f0 = __half22float2(*(__half2*)&v0);
                float2 f1 = __half22float2(*(__half2*)&v1);
                const int kb = tile * CPT + nc * 8;
                if (f0.x <= t0) { int p = atomicAdd(&candCnt[rbase], 1);     if (p < MAXCAND) candL[rbase][p]     = (short)(kb + 2 * q); }
                if (f0.y <= t0) { int p = atomicAdd(&candCnt[rbase], 1);     if (p < MAXCAND) candL[rbase][p]     = (short)(kb + 2 * q + 1); }
                if (f1.x <= t1) { int p = atomicAdd(&candCnt[rbase + 8], 1); if (p < MAXCAND) candL[rbase + 8][p] = (short)(kb + 2 * q); }
                if (f1.y <= t1) { int p = atomicAdd(&candCnt[rbase + 8], 1); if (p < MAXCAND) candL[rbase + 8][p] = (short)(kb + 2 * q + 1); }
            }
        }
    }
    __syncthreads();

    // ---- overflow list (R8/R13 measured ~1.3 cands/px; rare) ----
    if (t < MPX && candCnt[t] > MAXCAND) { int p = atomicAdd(&ovCnt, 1); ovList[p] = t; }
    __syncthreads();

    // =================== exact rescore (reference rounding) ===================
    if (t < MPX && candCnt[t] <= MAXCAND) {
        const float X = X_s[t];
        float best = CUDART_INF_F; int bk = 0;
        const int cnt = candCnt[t];
        for (int i = 0; i < cnt; i++) {
            int k = candL[t][i];
            const float* wk = weight + (size_t)k * C;
            float m = 0.f;
#pragma unroll
            for (int c = 0; c < C; c++) m = fmaf(xin[(size_t)c * HW + t], wk[c], m);
            float d = __fsub_rn(__fadd_rn(X, wsq_s[k]), __fadd_rn(m, m));
            if (d < best || (d == best && k < bk)) { best = d; bk = k; }
        }
        finI[t] = bk;
    }
    __syncthreads();

    // ---- block-cooperative exact fallback (~3us each, rare) ----
    for (int i = 0; i < ovCnt; i++) {
        const int px = ovList[i];
        const float X = X_s[px];
        float bd = CUDART_INF_F; int bk = 0;
#pragma unroll 1
        for (int kk = 0; kk < 8; kk++) {
            int k = t * 8 + kk;
            const float* wk = weight + (size_t)k * C;
            float m = 0.f;
#pragma unroll
            for (int c = 0; c < C; c++) m = fmaf(xin[(size_t)c * HW + px], wk[c], m);
            float d = __fsub_rn(__fadd_rn(X, wsq_s[k]), __fadd_rn(m, m));
            if (d < bd || (d == bd && k < bk)) { bd = d; bk = k; }
        }
#pragma unroll
        for (int o = 16; o > 0; o >>= 1) {
            float od = __shfl_down_sync(0xFFFFFFFFu, bd, o);
            int   ok = __shfl_down_sync(0xFFFFFFFFu, bk, o);
            if (od < bd || (od == bd && ok < bk)) { bd = od; bk = ok; }
        }
        if (lane == 0) { ovD[wid] = bd; ovK[wid] = bk; }
        __syncthreads();
        if (t == 0) {
            float fd = ovD[0]; int fk = ovK[0];
#pragma unroll
            for (int g = 1; g < 4; g++)
                if (ovD[g] < fd || (ovD[g] == fd && ovK[g] < fk)) { fd = ovD[g]; fk = ovK[g]; }
            finI[px] = fk;
        }
        __syncthreads();
    }

    // =================== epilogue ===================
    {
        const int px = t & 63;
        const int hf = t >> 6;                   // channel half
        const int bk = finI[px];
        const float* wb = weight + (size_t)bk * C + hf * 32;
        const float* xi = xin + (size_t)hf * 32 * HW + px;
        float* outq = out + (size_t)b * C * HW + (size_t)hf * 32 * HW + p0 + px;
        float lsum = 0.f;
#pragma unroll
        for (int c = 0; c < 32; c++) {
            float xv = xi[(size_t)c * HW];
            float dd = __fsub_rn(wb[c], xv);
            outq[(size_t)c * HW] = __fadd_rn(xv, dd);   // STE
            lsum = fmaf(dd, dd, lsum);
        }
        if (t < MPX) {
            const int n = blockIdx.x * MPX + t;
            out[OFF_IDX + n] = (float)finI[t];
            out[OFF_ENC + (size_t)n * K + finI[t]] = 1.0f;
            atomicAdd(&d_counts[finI[t]], 1);
        }
#pragma unroll
        for (int o = 16; o > 0; o >>= 1) lsum += __shfl_down_sync(0xFFFFFFFFu, lsum, o);
        if ((t & 31) == 0) redL[t >> 5] = lsum;
        __syncthreads();
        if (t == 0) d_loss_partial[blockIdx.x] = (redL[0] + redL[1]) + (redL[2] + redL[3]);
    }
}

// ---------------------------------------------------------------------------
// Finalize: loss + perplexity; re-zeroes d_counts for the next graph replay.
// ---------------------------------------------------------------------------
__global__ void vq_fin(float* __restrict__ out) {
    __shared__ float sh[K];
    __shared__ float sh2[NBLOCKS];
    int t = threadIdx.x;                  // 1024

    int cnt = d_counts[t];
    d_counts[t] = 0;
    float pr = (float)cnt * (1.0f / (float)NPIX);
    sh[t] = pr * logf(pr + 1e-10f);
    sh2[t] = d_loss_partial[t];
    __syncthreads();

    for (int s = K / 2; s > 0; s >>= 1) {
        if (t < s) { sh[t] += sh[t + s]; sh2[t] += sh2[t + s]; }
        __syncthreads();
    }
    if (t == 0) {
        out[OFF_LOSS] = 0.25f * sh2[0] / (float)QSIZE;
        out[OFF_PERP] = expf(-sh[0]);
    }
}

// ---------------------------------------------------------------------------
extern "C" void kernel_launch(void* const* d_in, const int* in_sizes, int n_in,
                              void* d_out, int out_size) {
    const float* in     = (const float*)d_in[0];
    const float* weight = (const float*)d_in[1];
    float* out = (float*)d_out;

    vq_prep<<<256, 128>>>(weight);
    vq_main<<<NBLOCKS, PPB>>>(in, weight, out);
    vq_fin<<<1, K>>>(out);
}